// round 9
// baseline (speedup 1.0000x reference)
#include <cuda_runtime.h>

// out[b, :] = table_bits[idx(b), :],  idx(b) = sum_k idx_bits[b,k] << (5-k)
// Table values are 0/1 pulses -> packed once into 64-bit masks (build kernel).
// Main kernel: masks staged in 512B smem (fill hidden under bits prefetch);
// per warp: 3 coalesced LDG.32 + 3 ballots + 8 x {broadcast LDS.64, ALU expand,
// contiguous STG.128}. Only LDG traffic left in L1tex queue: bits + stores.

#define BATCH   262144
#define THREADS 256
#define ROWS_PER_WARP 16
#define GRID (BATCH / (ROWS_PER_WARP * (THREADS / 32)))   // 2048 blocks

// Mask for table row r: column c (0..63) lives at bit (63 - c).
__device__ unsigned long long g_masks[64];

__global__ void build_masks_kernel(const float* __restrict__ table)
{
    int w    = (blockIdx.x * blockDim.x + threadIdx.x) >> 5;   // 0..63 table row
    int lane = threadIdx.x & 31;
    float v0 = table[w * 64 + lane];        // cols 0..31
    float v1 = table[w * 64 + 32 + lane];   // cols 32..63
    unsigned hi = __brev(__ballot_sync(0xFFFFFFFFu, v0 > 0.5f)); // col c -> bit 31-c
    unsigned lo = __brev(__ballot_sync(0xFFFFFFFFu, v1 > 0.5f));
    if (lane == 0)
        g_masks[w] = ((unsigned long long)hi << 32) | (unsigned long long)lo;
}

__device__ __forceinline__ float bit_to_1f(unsigned nib, int k)
{
    // nibble bit (3-k) -> 0.0f / 1.0f  (1.0f = 0x3F800000)
    return __int_as_float(((int)(nib << (28 + k)) >> 31) & 0x3F800000);
}

__global__ __launch_bounds__(THREADS)
void spike_lookup_kernel(const int* __restrict__ bits,    // BATCH*6
                         float4*    __restrict__ out4)    // BATCH*16
{
    __shared__ unsigned long long sm[64];   // 512 B mask table

    const int lane  = threadIdx.x & 31;
    const int gwarp = blockIdx.x * (THREADS / 32) + (threadIdx.x >> 5);

    // ---- Issue bits loads FIRST (DRAM latency hides under smem fill+barrier)
    const int* __restrict__ p = bits + gwarp * 96;   // 16 rows * 6 ints
    int v0 = p[lane];
    int v1 = p[lane + 32];
    int v2 = p[lane + 64];

    if (threadIdx.x < 64)
        sm[threadIdx.x] = g_masks[threadIdx.x];      // 64 x LDG.64, L1-hot
    __syncthreads();

    unsigned b0 = __ballot_sync(0xFFFFFFFFu, v0 != 0);  // int m -> bit m
    unsigned b1 = __ballot_sync(0xFFFFFFFFu, v1 != 0);
    unsigned b2 = __ballot_sync(0xFFFFFFFFu, v2 != 0);

    unsigned long long u01 = (unsigned long long)b0 | ((unsigned long long)b1 << 32);
    unsigned long long u12 = (unsigned long long)b1 | ((unsigned long long)b2 << 32);

    const int j    = lane & 15;        // float4 column within the 64-float row
    const int half = lane >> 4;        // row parity within the pair
    const int s    = 60 - 4 * j;       // cols 4j..4j+3 -> nibble bits 3..0

    // All 8 indices up front: pure ALU, no memory.
    int idxv[8];
    #pragma unroll
    for (int i = 0; i < 8; i++) {
        int r  = 2 * i + half;                    // local row 0..15
        int sh = 6 * r;
        unsigned vb = (r < 10) ? (unsigned)(u01 >> sh)
                               : (unsigned)(u12 >> (sh - 32));
        idxv[i] = (int)(__brev(vb & 63u) >> 26);  // k=0 is MSB (weight 32)
    }

    // LDS broadcast + expand + contiguous store; LDS is off the L1tex LDG queue.
    float4* __restrict__ dst = out4 + (long long)gwarp * 256 + lane;
    #pragma unroll
    for (int i = 0; i < 8; i++) {
        unsigned long long m = sm[idxv[i]];       // conflict-free broadcast LDS.64
        unsigned nib = (unsigned)(m >> s) & 0xFu;
        float4 v;
        v.x = bit_to_1f(nib, 0);
        v.y = bit_to_1f(nib, 1);
        v.z = bit_to_1f(nib, 2);
        v.w = bit_to_1f(nib, 3);
        dst[i * 32] = v;                          // 512B contiguous per warp
    }
}

extern "C" void kernel_launch(void* const* d_in, const int* in_sizes, int n_in,
                              void* d_out, int out_size)
{
    const float* table = (const float*)d_in[0];
    const int*   bits  = (const int*)d_in[1];
    float4*      out4  = (float4*)d_out;

    build_masks_kernel<<<2, 1024>>>(table);           // 64 warps, one per row
    spike_lookup_kernel<<<GRID, THREADS>>>(bits, out4);
}